// round 7
// baseline (speedup 1.0000x reference)
#include <cuda_runtime.h>
#include <cuda_bf16.h>
#include <cstdint>

// Dims fixed by setup_inputs: B=256, Q=256, S=512, D=1024
#define NB 256
#define NQ 256
#define NS 512
#define ND 1024
#define EPS 1e-8f
#define SLOPE 0.1f
#define SMOOTH 9.0f

__device__ float g_invnorm[NB * NS];
__device__ float g_invden[NB * NQ];

// Pre-converted bf16 hi/lo operand buffers (static device scratch)
__device__ __align__(16) __nv_bfloat16 g_qh[(size_t)NB * NQ * ND];  // 134MB
__device__ __align__(16) __nv_bfloat16 g_ql[(size_t)NB * NQ * ND];
__device__ __align__(16) __nv_bfloat16 g_ch[(size_t)NB * NS * ND];  // 268MB
__device__ __align__(16) __nv_bfloat16 g_cl[(size_t)NB * NS * ND];
__device__ __align__(16) __nv_bfloat16 g_ah[(size_t)NB * NS * NQ];  // 67MB
__device__ __align__(16) __nv_bfloat16 g_al[(size_t)NB * NS * NQ];

// ---------------------------------------------------------------------------
// helpers
// ---------------------------------------------------------------------------
__device__ __forceinline__ uint32_t smem_u32(const void* p) {
  uint32_t a;
  asm("{ .reg .u64 t; cvta.to.shared.u64 t, %1; cvt.u32.u64 %0, t; }" : "=r"(a) : "l"(p));
  return a;
}
__device__ __forceinline__ void cpa16(uint32_t dst, const void* src) {
  asm volatile("cp.async.cg.shared.global [%0], [%1], 16;" :: "r"(dst), "l"(src));
}
#define CP_COMMIT() asm volatile("cp.async.commit_group;" ::: "memory")
#define CP_WAIT1() asm volatile("cp.async.wait_group 1;" ::: "memory")
#define CP_WAIT0() asm volatile("cp.async.wait_group 0;" ::: "memory")

__device__ __forceinline__ void ldsm4(uint32_t* r, uint32_t addr) {
  asm volatile("ldmatrix.sync.aligned.m8n8.x4.shared.b16 {%0,%1,%2,%3}, [%4];"
               : "=r"(r[0]), "=r"(r[1]), "=r"(r[2]), "=r"(r[3]) : "r"(addr));
}
__device__ __forceinline__ void ldsm4t(uint32_t* r, uint32_t addr) {
  asm volatile("ldmatrix.sync.aligned.m8n8.x4.trans.shared.b16 {%0,%1,%2,%3}, [%4];"
               : "=r"(r[0]), "=r"(r[1]), "=r"(r[2]), "=r"(r[3]) : "r"(addr));
}
__device__ __forceinline__ void mma16816(float* c, const uint32_t* a, const uint32_t* b) {
  asm volatile(
      "mma.sync.aligned.m16n8k16.row.col.f32.bf16.bf16.f32 "
      "{%0,%1,%2,%3}, {%4,%5,%6,%7}, {%8,%9}, {%0,%1,%2,%3};"
      : "+f"(c[0]), "+f"(c[1]), "+f"(c[2]), "+f"(c[3])
      : "r"(a[0]), "r"(a[1]), "r"(a[2]), "r"(a[3]), "r"(b[0]), "r"(b[1]));
}

// fast fp32x4 -> bf16 hi (truncate) + bf16 lo (exact residual, RN)
__device__ __forceinline__ void cvt4_fast(float4 v, uint2& h, uint2& l) {
  uint32_t ax = __float_as_uint(v.x), ay = __float_as_uint(v.y);
  uint32_t az = __float_as_uint(v.z), aw = __float_as_uint(v.w);
  h.x = __byte_perm(ax, ay, 0x7632);
  h.y = __byte_perm(az, aw, 0x7632);
  float rx = v.x - __uint_as_float(ax & 0xFFFF0000u);
  float ry = v.y - __uint_as_float(ay & 0xFFFF0000u);
  float rz = v.z - __uint_as_float(az & 0xFFFF0000u);
  float rw = v.w - __uint_as_float(aw & 0xFFFF0000u);
  asm("cvt.rn.bf16x2.f32 %0, %1, %2;" : "=r"(l.x) : "f"(ry), "f"(rx));
  asm("cvt.rn.bf16x2.f32 %0, %1, %2;" : "=r"(l.y) : "f"(rw), "f"(rz));
}

// ---------------------------------------------------------------------------
// One-shot converters: fp32 -> hi/lo bf16 (grid exactly covers n/4)
// ---------------------------------------------------------------------------
__global__ __launch_bounds__(256) void k_convert_q(const float4* __restrict__ in) {
  size_t i = (size_t)blockIdx.x * blockDim.x + threadIdx.x;
  uint2 h, l;
  cvt4_fast(in[i], h, l);
  ((uint2*)g_qh)[i] = h;
  ((uint2*)g_ql)[i] = l;
}
__global__ __launch_bounds__(256) void k_convert_c(const float4* __restrict__ in) {
  size_t i = (size_t)blockIdx.x * blockDim.x + threadIdx.x;
  uint2 h, l;
  cvt4_fast(in[i], h, l);
  ((uint2*)g_ch)[i] = h;
  ((uint2*)g_cl)[i] = l;
}

// ---------------------------------------------------------------------------
// GEMM1: P[s][q] = leakyrelu( sum_d ctx[s][d]*qry[q][d] )
// m=s (A=ctx), n=q (B=qry), k=d, all bf16 hi/lo pre-converted.
// CTA 128x128, K-chunk 32, 8 warps (2m x 4n), 2-stage cp.async pipeline.
// ---------------------------------------------------------------------------
#define P1 40                          // smem row stride in bf16
#define BUF1 (128 * P1 * 2)            // 10240 B per buffer
#define ST1 (4 * BUF1)                 // 40960 B per stage

__global__ __launch_bounds__(256) void k_scores_mma(float* __restrict__ P) {
  extern __shared__ __align__(16) char sm[];
  const uint32_t sb = smem_u32(sm);

  const int t = threadIdx.x, w = t >> 5, lane = t & 31;
  const int b = blockIdx.z, q0 = blockIdx.x * 128, s0 = blockIdx.y * 128;
  const int warp_m = w >> 2, warp_n = w & 3;

  // cp.async task mapping: 512 tasks of 16B per buffer -> 2 per thread
  const int t2 = t * 2;
  const int r0 = t2 >> 2, e0 = t2 & 3;
  const int r1 = (t2 + 1) >> 2, e1 = (t2 + 1) & 3;
  const size_t aS0 = ((size_t)(b * NS + s0 + r0)) * ND + e0 * 8;
  const size_t aS1 = ((size_t)(b * NS + s0 + r1)) * ND + e1 * 8;
  const size_t bS0 = ((size_t)(b * NQ + q0 + r0)) * ND + e0 * 8;
  const size_t bS1 = ((size_t)(b * NQ + q0 + r1)) * ND + e1 * 8;
  const uint32_t d0w = r0 * (P1 * 2) + e0 * 16;
  const uint32_t d1w = r1 * (P1 * 2) + e1 * 16;

  // ldmatrix lane addressing (non-trans) — identical to verified R6 mapping
  const int g = lane >> 3, r8 = lane & 7;
  const int a_row = (g & 1) * 8 + r8, a_col = (g >> 1) * 8;
  const int b_row = (g >> 1) * 8 + r8, b_col = (g & 1) * 8;

  float acc[4][4][4];
#pragma unroll
  for (int i = 0; i < 4; i++)
#pragma unroll
    for (int j = 0; j < 4; j++)
#pragma unroll
      for (int k = 0; k < 4; k++) acc[i][j][k] = 0.0f;

#define FILL1(stage, kc)                                  \
  {                                                       \
    const uint32_t bs = sb + (stage) * ST1;               \
    cpa16(bs + d0w, g_ch + aS0 + (kc));                   \
    cpa16(bs + d1w, g_ch + aS1 + (kc));                   \
    cpa16(bs + BUF1 + d0w, g_cl + aS0 + (kc));            \
    cpa16(bs + BUF1 + d1w, g_cl + aS1 + (kc));            \
    cpa16(bs + 2 * BUF1 + d0w, g_qh + bS0 + (kc));        \
    cpa16(bs + 2 * BUF1 + d1w, g_qh + bS1 + (kc));        \
    cpa16(bs + 3 * BUF1 + d0w, g_ql + bS0 + (kc));        \
    cpa16(bs + 3 * BUF1 + d1w, g_ql + bS1 + (kc));        \
  }

  FILL1(0, 0);
  CP_COMMIT();

  const int NCH = ND / 32;  // 32 chunks
  for (int c = 0; c < NCH; c++) {
    if (c + 1 < NCH) {
      FILL1((c + 1) & 1, (c + 1) * 32);
      CP_COMMIT();
      CP_WAIT1();
    } else {
      CP_WAIT0();
    }
    __syncthreads();

    const uint32_t bs = sb + (c & 1) * ST1;
    const uint32_t aHi = bs, aLo = bs + BUF1;
    const uint32_t bHi = bs + 2 * BUF1, bLo = bs + 3 * BUF1;

#pragma unroll
    for (int kk = 0; kk < 32; kk += 16) {
      uint32_t bh[2][4], bl[2][4];
#pragma unroll
      for (int np = 0; np < 2; np++) {
        const uint32_t off = ((warp_n * 32 + np * 16 + b_row) * P1 + kk + b_col) * 2;
        ldsm4(bh[np], bHi + off);
        ldsm4(bl[np], bLo + off);
      }
#pragma unroll
      for (int mi = 0; mi < 4; mi++) {
        uint32_t ah[4], al[4];
        const uint32_t off = ((warp_m * 64 + mi * 16 + a_row) * P1 + kk + a_col) * 2;
        ldsm4(ah, aHi + off);
        ldsm4(al, aLo + off);
#pragma unroll
        for (int nt = 0; nt < 4; nt++) {
          const uint32_t* ph = &bh[nt >> 1][(nt & 1) * 2];
          const uint32_t* pl = &bl[nt >> 1][(nt & 1) * 2];
          mma16816(acc[mi][nt], ah, ph);
          mma16816(acc[mi][nt], ah, pl);
          mma16816(acc[mi][nt], al, ph);
        }
      }
    }
    __syncthreads();
  }

  // epilogue: leaky relu, write P[s][q]
  const int gm = lane >> 2, tg = lane & 3;
  float* Pb = P + (size_t)b * NS * NQ;
#pragma unroll
  for (int mi = 0; mi < 4; mi++) {
    const int sg = s0 + warp_m * 64 + mi * 16 + gm;
#pragma unroll
    for (int nt = 0; nt < 4; nt++) {
      const int qg = q0 + warp_n * 32 + nt * 8 + tg * 2;
      float* c = acc[mi][nt];
      float2 v0 = make_float2(c[0] > 0.f ? c[0] : SLOPE * c[0],
                              c[1] > 0.f ? c[1] : SLOPE * c[1]);
      float2 v1 = make_float2(c[2] > 0.f ? c[2] : SLOPE * c[2],
                              c[3] > 0.f ? c[3] : SLOPE * c[3]);
      *(float2*)(Pb + (size_t)sg * NQ + qg) = v0;
      *(float2*)(Pb + (size_t)(sg + 8) * NQ + qg) = v1;
    }
  }
}

// ---------------------------------------------------------------------------
// GEMM2: W[q][d] = sum_s attn[s][q]*ctx[s][d]
// m=q (attn via ldsm.trans), n=d (ctx via ldsm.trans), k=s. bf16 sources:
// attn hi/lo produced by k_final, ctx hi/lo from k_convert_c.
// ---------------------------------------------------------------------------
#define P2 136                          // smem row stride in bf16
#define BUF2 (32 * P2 * 2)              // 8704 B per buffer
#define ST2 (4 * BUF2)                  // 34816 B per stage

__global__ __launch_bounds__(256) void k_weighted_mma(float* __restrict__ W) {
  extern __shared__ __align__(16) char sm[];
  const uint32_t sb = smem_u32(sm);

  const int t = threadIdx.x, w = t >> 5, lane = t & 31;
  const int b = blockIdx.z, d0 = blockIdx.x * 128, q0 = blockIdx.y * 128;
  const int warp_m = w >> 2, warp_n = w & 3;

  // cp.async mapping: 512 tasks of 16B per buffer (32 rows x 16 segs)
  const int t2 = t * 2;
  const int r0 = t2 >> 4, e0 = t2 & 15;
  const int r1 = (t2 + 1) >> 4, e1 = (t2 + 1) & 15;
  const size_t aS0 = ((size_t)(b * NS + r0)) * NQ + q0 + e0 * 8;
  const size_t aS1 = ((size_t)(b * NS + r1)) * NQ + q0 + e1 * 8;
  const size_t bS0 = ((size_t)(b * NS + r0)) * ND + d0 + e0 * 8;
  const size_t bS1 = ((size_t)(b * NS + r1)) * ND + d0 + e1 * 8;
  const uint32_t d0w = r0 * (P2 * 2) + e0 * 16;
  const uint32_t d1w = r1 * (P2 * 2) + e1 * 16;

  // ldmatrix.trans lane addressing — identical to verified R6 mapping
  const int g = lane >> 3, r8 = lane & 7;
  const int a_k = (g >> 1) * 8 + r8, a_m = (g & 1) * 8;
  const int b_k = (g & 1) * 8 + r8, b_n = (g >> 1) * 8;

  float acc[4][4][4];
#pragma unroll
  for (int i = 0; i < 4; i++)
#pragma unroll
    for (int j = 0; j < 4; j++)
#pragma unroll
      for (int k = 0; k < 4; k++) acc[i][j][k] = 0.0f;

#define FILL2(stage, sc)                                            \
  {                                                                 \
    const uint32_t bs = sb + (stage) * ST2;                         \
    cpa16(bs + d0w, g_ah + aS0 + (size_t)(sc) * NQ);                \
    cpa16(bs + d1w, g_ah + aS1 + (size_t)(sc) * NQ);                \
    cpa16(bs + BUF2 + d0w, g_al + aS0 + (size_t)(sc) * NQ);         \
    cpa16(bs + BUF2 + d1w, g_al + aS1 + (size_t)(sc) * NQ);         \
    cpa16(bs + 2 * BUF2 + d0w, g_ch + bS0 + (size_t)(sc) * ND);     \
    cpa16(bs + 2 * BUF2 + d1w, g_ch + bS1 + (size_t)(sc) * ND);     \
    cpa16(bs + 3 * BUF2 + d0w, g_cl + bS0 + (size_t)(sc) * ND);     \
    cpa16(bs + 3 * BUF2 + d1w, g_cl + bS1 + (size_t)(sc) * ND);     \
  }

  FILL2(0, 0);
  CP_COMMIT();

  const int NCH = NS / 32;  // 16 chunks
  for (int c = 0; c < NCH; c++) {
    if (c + 1 < NCH) {
      FILL2((c + 1) & 1, (c + 1) * 32);
      CP_COMMIT();
      CP_WAIT1();
    } else {
      CP_WAIT0();
    }
    __syncthreads();

    const uint32_t bs = sb + (c & 1) * ST2;
    const uint32_t aHi = bs, aLo = bs + BUF2;
    const uint32_t bHi = bs + 2 * BUF2, bLo = bs + 3 * BUF2;

#pragma unroll
    for (int kk = 0; kk < 32; kk += 16) {
      uint32_t bh[2][4], bl[2][4];
#pragma unroll
      for (int np = 0; np < 2; np++) {
        const uint32_t off = ((kk + b_k) * P2 + warp_n * 32 + np * 16 + b_n) * 2;
        ldsm4t(bh[np], bHi + off);
        ldsm4t(bl[np], bLo + off);
      }
#pragma unroll
      for (int mi = 0; mi < 4; mi++) {
        uint32_t ah[4], al[4];
        const uint32_t off = ((kk + a_k) * P2 + warp_m * 64 + mi * 16 + a_m) * 2;
        ldsm4t(ah, aHi + off);
        ldsm4t(al, aLo + off);
#pragma unroll
        for (int nt = 0; nt < 4; nt++) {
          const uint32_t* ph = &bh[nt >> 1][(nt & 1) * 2];
          const uint32_t* pl = &bl[nt >> 1][(nt & 1) * 2];
          mma16816(acc[mi][nt], ah, ph);
          mma16816(acc[mi][nt], ah, pl);
          mma16816(acc[mi][nt], al, ph);
        }
      }
    }
    __syncthreads();
  }

  const int gm = lane >> 2, tg = lane & 3;
  float* Wb = W + (size_t)b * NQ * ND;
#pragma unroll
  for (int mi = 0; mi < 4; mi++) {
    const int qg = q0 + warp_m * 64 + mi * 16 + gm;
#pragma unroll
    for (int nt = 0; nt < 4; nt++) {
      const int dg = d0 + warp_n * 32 + nt * 8 + tg * 2;
      float* c = acc[mi][nt];
      *(float2*)(Wb + (size_t)qg * ND + dg) = make_float2(c[0], c[1]);
      *(float2*)(Wb + (size_t)(qg + 8) * ND + dg) = make_float2(c[2], c[3]);
    }
  }
}

// ---------------------------------------------------------------------------
// Elementwise chain
// ---------------------------------------------------------------------------
__global__ __launch_bounds__(256) void k_rownorm(const float* __restrict__ P) {
  const int row = blockIdx.x * 8 + (threadIdx.x >> 5);
  const int lane = threadIdx.x & 31;
  const float4* p = (const float4*)(P + (size_t)row * NQ);
  float4 a = p[lane];
  float4 b = p[lane + 32];
  float s = a.x * a.x + a.y * a.y + a.z * a.z + a.w * a.w +
            b.x * b.x + b.y * b.y + b.z * b.z + b.w * b.w;
#pragma unroll
  for (int o = 16; o > 0; o >>= 1) s += __shfl_xor_sync(0xffffffffu, s, o);
  if (lane == 0) g_invnorm[row] = 1.0f / (sqrtf(s) + EPS);
}

__global__ __launch_bounds__(256) void k_denom(const float* __restrict__ P) {
  const int b = blockIdx.x;
  const int q = threadIdx.x;
  const float* Pb = P + (size_t)b * NS * NQ + q;
  const float* iv = g_invnorm + b * NS;
  float d0 = 0.f, d1 = 0.f, d2 = 0.f, d3 = 0.f;
#pragma unroll 4
  for (int s = 0; s < NS; s += 4) {
    d0 += __expf(SMOOTH * Pb[(size_t)(s + 0) * NQ] * iv[s + 0]);
    d1 += __expf(SMOOTH * Pb[(size_t)(s + 1) * NQ] * iv[s + 1]);
    d2 += __expf(SMOOTH * Pb[(size_t)(s + 2) * NQ] * iv[s + 2]);
    d3 += __expf(SMOOTH * Pb[(size_t)(s + 3) * NQ] * iv[s + 3]);
  }
  g_invden[b * NQ + q] = 1.0f / (d0 + d1 + d2 + d3);
}

// finalize attn in place (fp32 output) AND emit bf16 hi/lo for GEMM2
__global__ __launch_bounds__(256) void k_final(float* __restrict__ P) {
  const size_t idx4 = (size_t)blockIdx.x * blockDim.x + threadIdx.x;
  const int q4 = (int)(idx4 & 63);
  const size_t row = idx4 >> 6;
  const int b = (int)(row >> 9);
  const float inv = g_invnorm[row];
  const float* id = g_invden + b * NQ + q4 * 4;
  float4 v = ((float4*)P)[idx4];
  v.x = __expf(SMOOTH * v.x * inv) * id[0];
  v.y = __expf(SMOOTH * v.y * inv) * id[1];
  v.z = __expf(SMOOTH * v.z * inv) * id[2];
  v.w = __expf(SMOOTH * v.w * inv) * id[3];
  ((float4*)P)[idx4] = v;
  uint2 h, l;
  cvt4_fast(v, h, l);
  ((uint2*)g_ah)[idx4] = h;
  ((uint2*)g_al)[idx4] = l;
}

// ---------------------------------------------------------------------------
// d_out = [ weighted (B,Q,D) | attnT (B,S,Q) ]
// ---------------------------------------------------------------------------
extern "C" void kernel_launch(void* const* d_in, const int* in_sizes, int n_in,
                              void* d_out, int out_size) {
  const float* qry = (const float*)d_in[0];  // (B,Q,D)
  const float* ctx = (const float*)d_in[1];  // (B,S,D)
  float* W = (float*)d_out;                         // (B,Q,D)
  float* P = (float*)d_out + (size_t)NB * NQ * ND;  // (B,S,Q)

  static int attr_done = 0;
  if (!attr_done) {
    cudaFuncSetAttribute(k_scores_mma, cudaFuncAttributeMaxDynamicSharedMemorySize, 2 * ST1);
    cudaFuncSetAttribute(k_weighted_mma, cudaFuncAttributeMaxDynamicSharedMemorySize, 2 * ST2);
    attr_done = 1;
  }

  k_convert_q<<<((size_t)NB * NQ * ND / 4) / 256, 256>>>((const float4*)qry);
  k_convert_c<<<((size_t)NB * NS * ND / 4) / 256, 256>>>((const float4*)ctx);

  {
    dim3 g(NQ / 128, NS / 128, NB);  // (2, 4, 256)
    k_scores_mma<<<g, 256, 2 * ST1>>>(P);
  }
  k_rownorm<<<(NB * NS) / 8, 256>>>(P);
  k_denom<<<NB, 256>>>(P);
  k_final<<<(size_t)NB * NS * NQ / 4 / 256, 256>>>(P);
  {
    dim3 g(ND / 128, NQ / 128, NB);  // (8, 2, 256)
    k_weighted_mma<<<g, 256, 2 * ST2>>>(W);
  }
}

// round 8
// speedup vs baseline: 1.4877x; 1.4877x over previous
#include <cuda_runtime.h>
#include <cuda_fp16.h>
#include <cstdint>

// Dims fixed by setup_inputs: B=256, Q=256, S=512, D=1024
#define NB 256
#define NQ 256
#define NS 512
#define ND 1024
#define EPS 1e-8f
#define SLOPE 0.1f
#define SMOOTH 9.0f

__device__ float g_invnorm[NB * NS];
__device__ float g_invden[NB * NQ];

// ---------------------------------------------------------------------------
// helpers
// ---------------------------------------------------------------------------
__device__ __forceinline__ void ldsm4(uint32_t* r, uint32_t addr) {
  asm volatile("ldmatrix.sync.aligned.m8n8.x4.shared.b16 {%0,%1,%2,%3}, [%4];"
               : "=r"(r[0]), "=r"(r[1]), "=r"(r[2]), "=r"(r[3]) : "r"(addr));
}
__device__ __forceinline__ void ldsm4t(uint32_t* r, uint32_t addr) {
  asm volatile("ldmatrix.sync.aligned.m8n8.x4.trans.shared.b16 {%0,%1,%2,%3}, [%4];"
               : "=r"(r[0]), "=r"(r[1]), "=r"(r[2]), "=r"(r[3]) : "r"(addr));
}
__device__ __forceinline__ void mma16816(float* c, const uint32_t* a, const uint32_t* b) {
  asm volatile(
      "mma.sync.aligned.m16n8k16.row.col.f32.f16.f16.f32 "
      "{%0,%1,%2,%3}, {%4,%5,%6,%7}, {%8,%9}, {%0,%1,%2,%3};"
      : "+f"(c[0]), "+f"(c[1]), "+f"(c[2]), "+f"(c[3])
      : "r"(a[0]), "r"(a[1]), "r"(a[2]), "r"(a[3]), "r"(b[0]), "r"(b[1]));
}
__device__ __forceinline__ uint32_t smem_u32(const void* p) {
  uint32_t a;
  asm("{ .reg .u64 t; cvta.to.shared.u64 t, %1; cvt.u32.u64 %0, t; }" : "=r"(a) : "l"(p));
  return a;
}

// fp32x4 -> fp16 hi (RN) + fp16 lo (exact residual, RN)
__device__ __forceinline__ void cvt4h_split(float4 v, uint2& h, uint2& l) {
  __half2 h0 = __floats2half2_rn(v.x, v.y);
  __half2 h1 = __floats2half2_rn(v.z, v.w);
  float2 f0 = __half22float2(h0);
  float2 f1 = __half22float2(h1);
  __half2 l0 = __floats2half2_rn(v.x - f0.x, v.y - f0.y);
  __half2 l1 = __floats2half2_rn(v.z - f1.x, v.w - f1.y);
  h.x = *(uint32_t*)&h0;
  h.y = *(uint32_t*)&h1;
  l.x = *(uint32_t*)&l0;
  l.y = *(uint32_t*)&l1;
}
// fp32x4 -> fp16x4 (RN)
__device__ __forceinline__ uint2 cvt4h(float4 v) {
  __half2 h0 = __floats2half2_rn(v.x, v.y);
  __half2 h1 = __floats2half2_rn(v.z, v.w);
  uint2 h;
  h.x = *(uint32_t*)&h0;
  h.y = *(uint32_t*)&h1;
  return h;
}

// ---------------------------------------------------------------------------
// GEMM1: P[s][q] = leakyrelu( sum_d ctx[s][d]*qry[q][d] )
// m=s (A=ctx, split hi/lo), n=q (B=qry, single fp16), k=d.
// CTA 128x128, K-chunk 32, 8 warps (2m x 4n). Register-staged prefetch.
// ---------------------------------------------------------------------------
#define P1 40  // smem row stride (half)

__global__ __launch_bounds__(256) void k_scores_mma(
    const float* __restrict__ qry, const float* __restrict__ ctx,
    float* __restrict__ P) {
  __shared__ __align__(16) __half sAhi[128 * P1], sAlo[128 * P1];
  __shared__ __align__(16) __half sBh[128 * P1];

  const int t = threadIdx.x, w = t >> 5, lane = t & 31;
  const int b = blockIdx.z, q0 = blockIdx.x * 128, s0 = blockIdx.y * 128;
  const int warp_m = w >> 2, warp_n = w & 3;

  const int lr = lane >> 3, lc8 = lane & 7;
  const float* Abase = ctx + ((size_t)(b * NS + s0)) * ND;  // rows = s
  const float* Bbase = qry + ((size_t)(b * NQ + q0)) * ND;  // rows = q

  const uint32_t aHi = smem_u32(sAhi), aLo = smem_u32(sAlo);
  const uint32_t bH = smem_u32(sBh);

  // ldmatrix lane addressing (non-trans) — verified R6 mapping
  const int g = lane >> 3, r8 = lane & 7;
  const int a_row = (g & 1) * 8 + r8, a_col = (g >> 1) * 8;
  const int b_row = (g >> 1) * 8 + r8, b_col = (g & 1) * 8;

  float acc[4][4][4];
#pragma unroll
  for (int i = 0; i < 4; i++)
#pragma unroll
    for (int j = 0; j < 4; j++)
#pragma unroll
      for (int k = 0; k < 4; k++) acc[i][j][k] = 0.0f;

  float4 stA[4], stB[4];
  const int col = lc8 * 4;
#pragma unroll
  for (int r4 = 0; r4 < 4; r4++) {
    const int row = r4 * 32 + w * 4 + lr;
    stA[r4] = *(const float4*)(Abase + (size_t)row * ND + col);
    stB[r4] = *(const float4*)(Bbase + (size_t)row * ND + col);
  }

  const int NCH = ND / 32;  // 32 chunks
  for (int c = 0; c < NCH; c++) {
    // convert staged regs -> smem
#pragma unroll
    for (int r4 = 0; r4 < 4; r4++) {
      const int row = r4 * 32 + w * 4 + lr;
      uint2 h, l;
      cvt4h_split(stA[r4], h, l);
      *(uint2*)&sAhi[row * P1 + col] = h;
      *(uint2*)&sAlo[row * P1 + col] = l;
      *(uint2*)&sBh[row * P1 + col] = cvt4h(stB[r4]);
    }
    __syncthreads();

    // issue next chunk's loads (latency hidden by mma phase)
    if (c + 1 < NCH) {
      const int kc = (c + 1) * 32;
#pragma unroll
      for (int r4 = 0; r4 < 4; r4++) {
        const int row = r4 * 32 + w * 4 + lr;
        stA[r4] = *(const float4*)(Abase + (size_t)row * ND + kc + col);
        stB[r4] = *(const float4*)(Bbase + (size_t)row * ND + kc + col);
      }
    }

#pragma unroll
    for (int kk = 0; kk < 32; kk += 16) {
      uint32_t bq[2][4];
#pragma unroll
      for (int np = 0; np < 2; np++) {
        const uint32_t off = ((warp_n * 32 + np * 16 + b_row) * P1 + kk + b_col) * 2;
        ldsm4(bq[np], bH + off);
      }
#pragma unroll
      for (int mi = 0; mi < 4; mi++) {
        uint32_t ah[4], al[4];
        const uint32_t off = ((warp_m * 64 + mi * 16 + a_row) * P1 + kk + a_col) * 2;
        ldsm4(ah, aHi + off);
        ldsm4(al, aLo + off);
#pragma unroll
        for (int nt = 0; nt < 4; nt++) {
          const uint32_t* pb = &bq[nt >> 1][(nt & 1) * 2];
          mma16816(acc[mi][nt], ah, pb);
          mma16816(acc[mi][nt], al, pb);
        }
      }
    }
    __syncthreads();
  }

  // epilogue: leaky relu, write P[s][q]
  const int gm = lane >> 2, tg = lane & 3;
  float* Pb = P + (size_t)b * NS * NQ;
#pragma unroll
  for (int mi = 0; mi < 4; mi++) {
    const int sg = s0 + warp_m * 64 + mi * 16 + gm;
#pragma unroll
    for (int nt = 0; nt < 4; nt++) {
      const int qg = q0 + warp_n * 32 + nt * 8 + tg * 2;
      float* c = acc[mi][nt];
      float2 v0 = make_float2(c[0] > 0.f ? c[0] : SLOPE * c[0],
                              c[1] > 0.f ? c[1] : SLOPE * c[1]);
      float2 v1 = make_float2(c[2] > 0.f ? c[2] : SLOPE * c[2],
                              c[3] > 0.f ? c[3] : SLOPE * c[3]);
      *(float2*)(Pb + (size_t)sg * NQ + qg) = v0;
      *(float2*)(Pb + (size_t)(sg + 8) * NQ + qg) = v1;
    }
  }
}

// ---------------------------------------------------------------------------
// GEMM2: W[q][d] = sum_s attn[s][q]*ctx[s][d]
// m=q (A=attn single fp16, ldsm.trans), n=d (B=ctx split hi/lo, ldsm.trans).
// ---------------------------------------------------------------------------
#define P2 136  // smem row stride (half)

__global__ __launch_bounds__(256) void k_weighted_mma(
    const float* __restrict__ attn, const float* __restrict__ ctx,
    float* __restrict__ W) {
  __shared__ __align__(16) __half sAh[32 * P2];
  __shared__ __align__(16) __half sBhi[32 * P2], sBlo[32 * P2];

  const int t = threadIdx.x, w = t >> 5, lane = t & 31;
  const int b = blockIdx.z, d0 = blockIdx.x * 128, q0 = blockIdx.y * 128;
  const int warp_m = w >> 2, warp_n = w & 3;

  const int lr = lane >> 3, lc8 = lane & 7;
  const float* Ab = attn + (size_t)b * NS * NQ;
  const float* Bb = ctx + (size_t)b * NS * ND;

  const uint32_t aH = smem_u32(sAh);
  const uint32_t bHi = smem_u32(sBhi), bLo = smem_u32(sBlo);

  // ldmatrix.trans lane addressing — verified R6 mapping
  const int g = lane >> 3, r8 = lane & 7;
  const int a_k = (g >> 1) * 8 + r8, a_m = (g & 1) * 8;
  const int b_k = (g & 1) * 8 + r8, b_n = (g >> 1) * 8;

  float acc[4][4][4];
#pragma unroll
  for (int i = 0; i < 4; i++)
#pragma unroll
    for (int j = 0; j < 4; j++)
#pragma unroll
      for (int k = 0; k < 4; k++) acc[i][j][k] = 0.0f;

  float4 stA[4], stB[4];
  const int row = w * 4 + lr;  // 0..31
#pragma unroll
  for (int cr = 0; cr < 4; cr++) {
    const int col = cr * 32 + lc8 * 4;
    stA[cr] = *(const float4*)(Ab + (size_t)row * NQ + q0 + col);
    stB[cr] = *(const float4*)(Bb + (size_t)row * ND + d0 + col);
  }

  const int NCH = NS / 32;  // 16 chunks
  for (int c = 0; c < NCH; c++) {
#pragma unroll
    for (int cr = 0; cr < 4; cr++) {
      const int col = cr * 32 + lc8 * 4;
      *(uint2*)&sAh[row * P2 + col] = cvt4h(stA[cr]);
      uint2 h, l;
      cvt4h_split(stB[cr], h, l);
      *(uint2*)&sBhi[row * P2 + col] = h;
      *(uint2*)&sBlo[row * P2 + col] = l;
    }
    __syncthreads();

    if (c + 1 < NCH) {
      const int sc = (c + 1) * 32;
#pragma unroll
      for (int cr = 0; cr < 4; cr++) {
        const int col = cr * 32 + lc8 * 4;
        stA[cr] = *(const float4*)(Ab + (size_t)(sc + row) * NQ + q0 + col);
        stB[cr] = *(const float4*)(Bb + (size_t)(sc + row) * ND + d0 + col);
      }
    }

#pragma unroll
    for (int kk = 0; kk < 32; kk += 16) {
      uint32_t bh[2][4], bl[2][4];
#pragma unroll
      for (int np = 0; np < 2; np++) {
        const uint32_t off = ((kk + b_k) * P2 + warp_n * 32 + np * 16 + b_n) * 2;
        ldsm4t(bh[np], bHi + off);
        ldsm4t(bl[np], bLo + off);
      }
#pragma unroll
      for (int mi = 0; mi < 4; mi++) {
        uint32_t ah[4];
        const uint32_t off = ((kk + a_k) * P2 + warp_m * 64 + mi * 16 + a_m) * 2;
        ldsm4t(ah, aH + off);
#pragma unroll
        for (int nt = 0; nt < 4; nt++) {
          const uint32_t* ph = &bh[nt >> 1][(nt & 1) * 2];
          const uint32_t* pl = &bl[nt >> 1][(nt & 1) * 2];
          mma16816(acc[mi][nt], ah, ph);
          mma16816(acc[mi][nt], ah, pl);
        }
      }
    }
    __syncthreads();
  }

  const int gm = lane >> 2, tg = lane & 3;
  float* Wb = W + (size_t)b * NQ * ND;
#pragma unroll
  for (int mi = 0; mi < 4; mi++) {
    const int qg = q0 + warp_m * 64 + mi * 16 + gm;
#pragma unroll
    for (int nt = 0; nt < 4; nt++) {
      const int dg = d0 + warp_n * 32 + nt * 8 + tg * 2;
      float* c = acc[mi][nt];
      *(float2*)(Wb + (size_t)qg * ND + dg) = make_float2(c[0], c[1]);
      *(float2*)(Wb + (size_t)(qg + 8) * ND + dg) = make_float2(c[2], c[3]);
    }
  }
}

// ---------------------------------------------------------------------------
// Elementwise chain (unchanged)
// ---------------------------------------------------------------------------
__global__ __launch_bounds__(256) void k_rownorm(const float* __restrict__ P) {
  const int row = blockIdx.x * 8 + (threadIdx.x >> 5);
  const int lane = threadIdx.x & 31;
  const float4* p = (const float4*)(P + (size_t)row * NQ);
  float4 a = p[lane];
  float4 b = p[lane + 32];
  float s = a.x * a.x + a.y * a.y + a.z * a.z + a.w * a.w +
            b.x * b.x + b.y * b.y + b.z * b.z + b.w * b.w;
#pragma unroll
  for (int o = 16; o > 0; o >>= 1) s += __shfl_xor_sync(0xffffffffu, s, o);
  if (lane == 0) g_invnorm[row] = 1.0f / (sqrtf(s) + EPS);
}

__global__ __launch_bounds__(256) void k_denom(const float* __restrict__ P) {
  const int b = blockIdx.x;
  const int q = threadIdx.x;
  const float* Pb = P + (size_t)b * NS * NQ + q;
  const float* iv = g_invnorm + b * NS;
  float d0 = 0.f, d1 = 0.f, d2 = 0.f, d3 = 0.f;
#pragma unroll 4
  for (int s = 0; s < NS; s += 4) {
    d0 += __expf(SMOOTH * Pb[(size_t)(s + 0) * NQ] * iv[s + 0]);
    d1 += __expf(SMOOTH * Pb[(size_t)(s + 1) * NQ] * iv[s + 1]);
    d2 += __expf(SMOOTH * Pb[(size_t)(s + 2) * NQ] * iv[s + 2]);
    d3 += __expf(SMOOTH * Pb[(size_t)(s + 3) * NQ] * iv[s + 3]);
  }
  g_invden[b * NQ + q] = 1.0f / (d0 + d1 + d2 + d3);
}

__global__ __launch_bounds__(256) void k_final(float* __restrict__ P) {
  const size_t idx4 = (size_t)blockIdx.x * blockDim.x + threadIdx.x;
  const int q4 = (int)(idx4 & 63);
  const size_t row = idx4 >> 6;
  const int b = (int)(row >> 9);
  const float inv = g_invnorm[row];
  const float* id = g_invden + b * NQ + q4 * 4;
  float4 v = ((float4*)P)[idx4];
  v.x = __expf(SMOOTH * v.x * inv) * id[0];
  v.y = __expf(SMOOTH * v.y * inv) * id[1];
  v.z = __expf(SMOOTH * v.z * inv) * id[2];
  v.w = __expf(SMOOTH * v.w * inv) * id[3];
  ((float4*)P)[idx4] = v;
}

// ---------------------------------------------------------------------------
// d_out = [ weighted (B,Q,D) | attnT (B,S,Q) ]; attnT region doubles as
// scratch for the score matrix through the softmax chain.
// ---------------------------------------------------------------------------
extern "C" void kernel_launch(void* const* d_in, const int* in_sizes, int n_in,
                              void* d_out, int out_size) {
  const float* qry = (const float*)d_in[0];  // (B,Q,D)
  const float* ctx = (const float*)d_in[1];  // (B,S,D)
  float* W = (float*)d_out;                         // (B,Q,D)
  float* P = (float*)d_out + (size_t)NB * NQ * ND;  // (B,S,Q)

  {
    dim3 g(NQ / 128, NS / 128, NB);  // (2, 4, 256)
    k_scores_mma<<<g, 256>>>(qry, ctx, P);
  }
  k_rownorm<<<(NB * NS) / 8, 256>>>(P);
  k_denom<<<NB, 256>>>(P);
  k_final<<<(size_t)NB * NS * NQ / 4 / 256, 256>>>(P);
  {
    dim3 g(ND / 128, NQ / 128, NB);  // (8, 2, 256)
    k_weighted_mma<<<g, 256>>>(P, ctx, W);
  }
}

// round 9
// speedup vs baseline: 2.3924x; 1.6082x over previous
#include <cuda_runtime.h>
#include <cuda_fp16.h>
#include <cstdint>

// Dims fixed by setup_inputs: B=256, Q=256, S=512, D=1024
#define NB 256
#define NQ 256
#define NS 512
#define ND 1024
#define EPS 1e-8f
#define SLOPE 0.1f
#define SMOOTH 9.0f

__device__ float g_invnorm[NB * NS];
__device__ float g_invden[NB * NQ];
__device__ float g_part[2][NB * NS];  // per-(q-block) partial sum of squares

// ---------------------------------------------------------------------------
// helpers
// ---------------------------------------------------------------------------
__device__ __forceinline__ void ldsm4(uint32_t* r, uint32_t addr) {
  asm volatile("ldmatrix.sync.aligned.m8n8.x4.shared.b16 {%0,%1,%2,%3}, [%4];"
               : "=r"(r[0]), "=r"(r[1]), "=r"(r[2]), "=r"(r[3]) : "r"(addr));
}
__device__ __forceinline__ void ldsm4t(uint32_t* r, uint32_t addr) {
  asm volatile("ldmatrix.sync.aligned.m8n8.x4.trans.shared.b16 {%0,%1,%2,%3}, [%4];"
               : "=r"(r[0]), "=r"(r[1]), "=r"(r[2]), "=r"(r[3]) : "r"(addr));
}
__device__ __forceinline__ void mma16816(float* c, const uint32_t* a, const uint32_t* b) {
  asm volatile(
      "mma.sync.aligned.m16n8k16.row.col.f32.f16.f16.f32 "
      "{%0,%1,%2,%3}, {%4,%5,%6,%7}, {%8,%9}, {%0,%1,%2,%3};"
      : "+f"(c[0]), "+f"(c[1]), "+f"(c[2]), "+f"(c[3])
      : "r"(a[0]), "r"(a[1]), "r"(a[2]), "r"(a[3]), "r"(b[0]), "r"(b[1]));
}
__device__ __forceinline__ uint32_t smem_u32(const void* p) {
  uint32_t a;
  asm("{ .reg .u64 t; cvta.to.shared.u64 t, %1; cvt.u32.u64 %0, t; }" : "=r"(a) : "l"(p));
  return a;
}
// fp32x4 -> fp16x4 (RN)
__device__ __forceinline__ uint2 cvt4h(float4 v) {
  __half2 h0 = __floats2half2_rn(v.x, v.y);
  __half2 h1 = __floats2half2_rn(v.z, v.w);
  uint2 h;
  h.x = *(uint32_t*)&h0;
  h.y = *(uint32_t*)&h1;
  return h;
}

// ---------------------------------------------------------------------------
// GEMM1: P[s][q] = leakyrelu( sum_d ctx[s][d]*qry[q][d] ), fp16 x fp16.
// m=s (A=ctx), n=q (B=qry), k=d. CTA 128x128, K-chunk 32, 8 warps (2m x 4n).
// Epilogue also accumulates per-row sum of leaky^2 into g_part (deterministic).
// ---------------------------------------------------------------------------
#define P1 40  // smem row stride (half)

__global__ __launch_bounds__(256) void k_scores_mma(
    const float* __restrict__ qry, const float* __restrict__ ctx,
    float* __restrict__ P) {
  __shared__ __align__(16) __half sAh[128 * P1];
  __shared__ __align__(16) __half sBh[128 * P1];
  __shared__ float sred[4][128];

  const int t = threadIdx.x, w = t >> 5, lane = t & 31;
  const int b = blockIdx.z, qblk = blockIdx.x, q0 = qblk * 128, s0 = blockIdx.y * 128;
  const int warp_m = w >> 2, warp_n = w & 3;

  const int lr = lane >> 3, lc8 = lane & 7;
  const float* Abase = ctx + ((size_t)(b * NS + s0)) * ND;  // rows = s
  const float* Bbase = qry + ((size_t)(b * NQ + q0)) * ND;  // rows = q

  const uint32_t aH = smem_u32(sAh);
  const uint32_t bH = smem_u32(sBh);

  // ldmatrix lane addressing (non-trans) — verified mapping
  const int g = lane >> 3, r8 = lane & 7;
  const int a_row = (g & 1) * 8 + r8, a_col = (g >> 1) * 8;
  const int b_row = (g >> 1) * 8 + r8, b_col = (g & 1) * 8;

  float acc[4][4][4];
#pragma unroll
  for (int i = 0; i < 4; i++)
#pragma unroll
    for (int j = 0; j < 4; j++)
#pragma unroll
      for (int k = 0; k < 4; k++) acc[i][j][k] = 0.0f;

  float4 stA[4], stB[4];
  const int col = lc8 * 4;
#pragma unroll
  for (int r4 = 0; r4 < 4; r4++) {
    const int row = r4 * 32 + w * 4 + lr;
    stA[r4] = *(const float4*)(Abase + (size_t)row * ND + col);
    stB[r4] = *(const float4*)(Bbase + (size_t)row * ND + col);
  }

  const int NCH = ND / 32;  // 32 chunks
  for (int c = 0; c < NCH; c++) {
#pragma unroll
    for (int r4 = 0; r4 < 4; r4++) {
      const int row = r4 * 32 + w * 4 + lr;
      *(uint2*)&sAh[row * P1 + col] = cvt4h(stA[r4]);
      *(uint2*)&sBh[row * P1 + col] = cvt4h(stB[r4]);
    }
    __syncthreads();

    if (c + 1 < NCH) {  // prefetch next chunk into regs
      const int kc = (c + 1) * 32;
#pragma unroll
      for (int r4 = 0; r4 < 4; r4++) {
        const int row = r4 * 32 + w * 4 + lr;
        stA[r4] = *(const float4*)(Abase + (size_t)row * ND + kc + col);
        stB[r4] = *(const float4*)(Bbase + (size_t)row * ND + kc + col);
      }
    }

#pragma unroll
    for (int kk = 0; kk < 32; kk += 16) {
      uint32_t bq[2][4];
#pragma unroll
      for (int np = 0; np < 2; np++) {
        const uint32_t off = ((warp_n * 32 + np * 16 + b_row) * P1 + kk + b_col) * 2;
        ldsm4(bq[np], bH + off);
      }
#pragma unroll
      for (int mi = 0; mi < 4; mi++) {
        uint32_t ah[4];
        const uint32_t off = ((warp_m * 64 + mi * 16 + a_row) * P1 + kk + a_col) * 2;
        ldsm4(ah, aH + off);
#pragma unroll
        for (int nt = 0; nt < 4; nt++) {
          mma16816(acc[mi][nt], ah, &bq[nt >> 1][(nt & 1) * 2]);
        }
      }
    }
    __syncthreads();
  }

  // epilogue: leaky relu, write P[s][q], accumulate row sums of squares
  const int gm = lane >> 2, tg = lane & 3;
  float* Pb = P + (size_t)b * NS * NQ;
  float rsum[4][2];
#pragma unroll
  for (int mi = 0; mi < 4; mi++) {
    rsum[mi][0] = 0.0f;
    rsum[mi][1] = 0.0f;
    const int sg = s0 + warp_m * 64 + mi * 16 + gm;
#pragma unroll
    for (int nt = 0; nt < 4; nt++) {
      const int qg = q0 + warp_n * 32 + nt * 8 + tg * 2;
      float* c = acc[mi][nt];
      float2 v0 = make_float2(c[0] > 0.f ? c[0] : SLOPE * c[0],
                              c[1] > 0.f ? c[1] : SLOPE * c[1]);
      float2 v1 = make_float2(c[2] > 0.f ? c[2] : SLOPE * c[2],
                              c[3] > 0.f ? c[3] : SLOPE * c[3]);
      *(float2*)(Pb + (size_t)sg * NQ + qg) = v0;
      *(float2*)(Pb + (size_t)(sg + 8) * NQ + qg) = v1;
      rsum[mi][0] += v0.x * v0.x + v0.y * v0.y;
      rsum[mi][1] += v1.x * v1.x + v1.y * v1.y;
    }
  }
  // reduce over tg (4 lanes share a row)
#pragma unroll
  for (int mi = 0; mi < 4; mi++) {
#pragma unroll
    for (int h = 0; h < 2; h++) {
      float s = rsum[mi][h];
      s += __shfl_xor_sync(0xffffffffu, s, 1);
      s += __shfl_xor_sync(0xffffffffu, s, 2);
      if (tg == 0) sred[warp_n][warp_m * 64 + mi * 16 + h * 8 + gm] = s;
    }
  }
  __syncthreads();
  if (t < 128) {
    float s = sred[0][t] + sred[1][t] + sred[2][t] + sred[3][t];
    g_part[qblk][(size_t)b * NS + s0 + t] = s;
  }
}

// combine the two q-block partials -> invnorm
__global__ __launch_bounds__(256) void k_comb() {
  const int i = blockIdx.x * 256 + threadIdx.x;
  g_invnorm[i] = 1.0f / (sqrtf(g_part[0][i] + g_part[1][i]) + EPS);
}

// ---------------------------------------------------------------------------
// GEMM2: W[q][d] = sum_s attn[s][q]*ctx[s][d], fp16 x fp16.
// m=q (attn via ldsm.trans), n=d (ctx via ldsm.trans), k=s.
// ---------------------------------------------------------------------------
#define P2 136  // smem row stride (half)

__global__ __launch_bounds__(256) void k_weighted_mma(
    const float* __restrict__ attn, const float* __restrict__ ctx,
    float* __restrict__ W) {
  __shared__ __align__(16) __half sAh[32 * P2];
  __shared__ __align__(16) __half sBh[32 * P2];

  const int t = threadIdx.x, w = t >> 5, lane = t & 31;
  const int b = blockIdx.z, d0 = blockIdx.x * 128, q0 = blockIdx.y * 128;
  const int warp_m = w >> 2, warp_n = w & 3;

  const int lr = lane >> 3, lc8 = lane & 7;
  const float* Ab = attn + (size_t)b * NS * NQ;
  const float* Bb = ctx + (size_t)b * NS * ND;

  const uint32_t aH = smem_u32(sAh);
  const uint32_t bH = smem_u32(sBh);

  // ldmatrix.trans lane addressing — verified mapping
  const int g = lane >> 3, r8 = lane & 7;
  const int a_k = (g >> 1) * 8 + r8, a_m = (g & 1) * 8;
  const int b_k = (g & 1) * 8 + r8, b_n = (g >> 1) * 8;

  float acc[4][4][4];
#pragma unroll
  for (int i = 0; i < 4; i++)
#pragma unroll
    for (int j = 0; j < 4; j++)
#pragma unroll
      for (int k = 0; k < 4; k++) acc[i][j][k] = 0.0f;

  float4 stA[4], stB[4];
  const int row = w * 4 + lr;  // 0..31
#pragma unroll
  for (int cr = 0; cr < 4; cr++) {
    const int col = cr * 32 + lc8 * 4;
    stA[cr] = *(const float4*)(Ab + (size_t)row * NQ + q0 + col);
    stB[cr] = *(const float4*)(Bb + (size_t)row * ND + d0 + col);
  }

  const int NCH = NS / 32;  // 16 chunks
  for (int c = 0; c < NCH; c++) {
#pragma unroll
    for (int cr = 0; cr < 4; cr++) {
      const int col = cr * 32 + lc8 * 4;
      *(uint2*)&sAh[row * P2 + col] = cvt4h(stA[cr]);
      *(uint2*)&sBh[row * P2 + col] = cvt4h(stB[cr]);
    }
    __syncthreads();

    if (c + 1 < NCH) {
      const int sc = (c + 1) * 32;
#pragma unroll
      for (int cr = 0; cr < 4; cr++) {
        const int col = cr * 32 + lc8 * 4;
        stA[cr] = *(const float4*)(Ab + (size_t)(sc + row) * NQ + q0 + col);
        stB[cr] = *(const float4*)(Bb + (size_t)(sc + row) * ND + d0 + col);
      }
    }

#pragma unroll
    for (int kk = 0; kk < 32; kk += 16) {
      uint32_t bq[2][4];
#pragma unroll
      for (int np = 0; np < 2; np++) {
        const uint32_t off = ((kk + b_k) * P2 + warp_n * 32 + np * 16 + b_n) * 2;
        ldsm4t(bq[np], bH + off);
      }
#pragma unroll
      for (int mi = 0; mi < 4; mi++) {
        uint32_t ah[4];
        const uint32_t off = ((kk + a_k) * P2 + warp_m * 64 + mi * 16 + a_m) * 2;
        ldsm4t(ah, aH + off);
#pragma unroll
        for (int nt = 0; nt < 4; nt++) {
          mma16816(acc[mi][nt], ah, &bq[nt >> 1][(nt & 1) * 2]);
        }
      }
    }
    __syncthreads();
  }

  const int gm = lane >> 2, tg = lane & 3;
  float* Wb = W + (size_t)b * NQ * ND;
#pragma unroll
  for (int mi = 0; mi < 4; mi++) {
    const int qg = q0 + warp_m * 64 + mi * 16 + gm;
#pragma unroll
    for (int nt = 0; nt < 4; nt++) {
      const int dg = d0 + warp_n * 32 + nt * 8 + tg * 2;
      float* c = acc[mi][nt];
      *(float2*)(Wb + (size_t)qg * ND + dg) = make_float2(c[0], c[1]);
      *(float2*)(Wb + (size_t)(qg + 8) * ND + dg) = make_float2(c[2], c[3]);
    }
  }
}

// ---------------------------------------------------------------------------
// Softmax chain
// ---------------------------------------------------------------------------
__global__ __launch_bounds__(256) void k_denom(const float* __restrict__ P) {
  const int b = blockIdx.x;
  const int q = threadIdx.x;
  const float* Pb = P + (size_t)b * NS * NQ + q;
  const float* iv = g_invnorm + b * NS;
  float d0 = 0.f, d1 = 0.f, d2 = 0.f, d3 = 0.f;
#pragma unroll 4
  for (int s = 0; s < NS; s += 4) {
    d0 += __expf(SMOOTH * Pb[(size_t)(s + 0) * NQ] * iv[s + 0]);
    d1 += __expf(SMOOTH * Pb[(size_t)(s + 1) * NQ] * iv[s + 1]);
    d2 += __expf(SMOOTH * Pb[(size_t)(s + 2) * NQ] * iv[s + 2]);
    d3 += __expf(SMOOTH * Pb[(size_t)(s + 3) * NQ] * iv[s + 3]);
  }
  g_invden[b * NQ + q] = 1.0f / (d0 + d1 + d2 + d3);
}

__global__ __launch_bounds__(256) void k_final(float* __restrict__ P) {
  const size_t idx4 = (size_t)blockIdx.x * blockDim.x + threadIdx.x;
  const int q4 = (int)(idx4 & 63);
  const size_t row = idx4 >> 6;
  const int b = (int)(row >> 9);
  const float inv = g_invnorm[row];
  const float* id = g_invden + b * NQ + q4 * 4;
  float4 v = ((float4*)P)[idx4];
  v.x = __expf(SMOOTH * v.x * inv) * id[0];
  v.y = __expf(SMOOTH * v.y * inv) * id[1];
  v.z = __expf(SMOOTH * v.z * inv) * id[2];
  v.w = __expf(SMOOTH * v.w * inv) * id[3];
  ((float4*)P)[idx4] = v;
}

// ---------------------------------------------------------------------------
// d_out = [ weighted (B,Q,D) | attnT (B,S,Q) ]; attnT region doubles as
// scratch for the score matrix through the softmax chain.
// ---------------------------------------------------------------------------
extern "C" void kernel_launch(void* const* d_in, const int* in_sizes, int n_in,
                              void* d_out, int out_size) {
  const float* qry = (const float*)d_in[0];  // (B,Q,D)
  const float* ctx = (const float*)d_in[1];  // (B,S,D)
  float* W = (float*)d_out;                         // (B,Q,D)
  float* P = (float*)d_out + (size_t)NB * NQ * ND;  // (B,S,Q)

  {
    dim3 g(NQ / 128, NS / 128, NB);  // (2, 4, 256)
    k_scores_mma<<<g, 256>>>(qry, ctx, P);
  }
  k_comb<<<(NB * NS) / 256, 256>>>();
  k_denom<<<NB, 256>>>(P);
  k_final<<<(size_t)NB * NS * NQ / 4 / 256, 256>>>(P);
  {
    dim3 g(ND / 128, NQ / 128, NB);  // (8, 2, 256)
    k_weighted_mma<<<g, 256>>>(P, ctx, W);
  }
}